// round 1
// baseline (speedup 1.0000x reference)
#include <cuda_runtime.h>
#include <cuda_bf16.h>
#include <cstdint>

#define FULL 0xFFFFFFFFu

// Scratch for qlayer outputs: [BS, 64] floats. BS = 2048 here; headroom to 4096 rows.
__device__ float g_q[1 << 18];

// ---------------------------------------------------------------------------
// State layout: one warp per token. Lane l holds amplitudes with flat index
// (k<<5)|l for k in 0..7, as float2 (re, im). Wire w <-> bit (7-w) of flat idx.
// Bits 5..7 = register bits (k), bits 0..4 = lane bits.
// ---------------------------------------------------------------------------

// RX on a register bit RB (0..2): in-lane pair butterfly.
// new0 = c*a0 - i s * a1 ; new1 = c*a1 - i s * a0
template<int RB>
__device__ __forceinline__ void rx_reg(float2 (&a)[8], float c, float s) {
#pragma unroll
    for (int k0 = 0; k0 < 8; ++k0) {
        if (k0 & (1 << RB)) continue;
        const int k1 = k0 | (1 << RB);
        float2 A = a[k0], B = a[k1];
        a[k0].x = fmaf(c, A.x,  s * B.y);
        a[k0].y = fmaf(c, A.y, -s * B.x);
        a[k1].x = fmaf(c, B.x,  s * A.y);
        a[k1].y = fmaf(c, B.y, -s * A.x);
    }
}

// RX on a lane bit B (0..4): symmetric, new_me = c*me + (-i s)*partner.
template<int B>
__device__ __forceinline__ void rx_lane(float2 (&a)[8], float c, float s) {
#pragma unroll
    for (int k = 0; k < 8; ++k) {
        float px = __shfl_xor_sync(FULL, a[k].x, 1 << B);
        float py = __shfl_xor_sync(FULL, a[k].y, 1 << B);
        float nx = fmaf(c, a[k].x,  s * py);
        float ny = fmaf(c, a[k].y, -s * px);
        a[k].x = nx; a[k].y = ny;
    }
}

template<int W>
__device__ __forceinline__ void rx_wire(float2 (&a)[8], float c, float s) {
    constexpr int B = 7 - W;
    if constexpr (B >= 5) rx_reg<B - 5>(a, c, s);
    else                  rx_lane<B>(a, c, s);
}

// RZ on wire W: diagonal, multiply amp by (c + i*t), t = bit ? s : -s.
template<int W>
__device__ __forceinline__ void rz_wire(float2 (&a)[8], int lane, float c, float s) {
    constexpr int B = 7 - W;
#pragma unroll
    for (int k = 0; k < 8; ++k) {
        int bit;
        if constexpr (B >= 5) bit = (k >> (B - 5)) & 1;
        else                  bit = (lane >> B) & 1;
        float t = bit ? s : -s;
        float nx = fmaf(a[k].x, c, -a[k].y * t);
        float ny = fmaf(a[k].y, c,  a[k].x * t);
        a[k].x = nx; a[k].y = ny;
    }
}

// CNOT with control bit BC, target bit BT (flat-index bit positions).
template<int BC, int BT>
__device__ __forceinline__ void cnot(float2 (&a)[8], int lane) {
    if constexpr (BC >= 5 && BT >= 5) {
        // both register bits: pure in-lane transposition
#pragma unroll
        for (int k = 0; k < 8; ++k) {
            if ((k & (1 << (BC - 5))) && !(k & (1 << (BT - 5)))) {
                const int k2 = k | (1 << (BT - 5));
                float2 t = a[k]; a[k] = a[k2]; a[k2] = t;
            }
        }
    } else if constexpr (BC >= 5 && BT < 5) {
        // control = register bit, target = lane bit: shuffle those k with ctrl set
#pragma unroll
        for (int k = 0; k < 8; ++k) {
            if (k & (1 << (BC - 5))) {
                a[k].x = __shfl_xor_sync(FULL, a[k].x, 1 << BT);
                a[k].y = __shfl_xor_sync(FULL, a[k].y, 1 << BT);
            }
        }
    } else if constexpr (BC < 5 && BT >= 5) {
        // control = lane bit, target = register bit: predicated local swap
        const bool cset = (lane >> BC) & 1;
#pragma unroll
        for (int k0 = 0; k0 < 8; ++k0) {
            if (!(k0 & (1 << (BT - 5)))) {
                const int k1 = k0 | (1 << (BT - 5));
                float2 A = a[k0], B = a[k1];
                a[k0] = cset ? B : A;
                a[k1] = cset ? A : B;
            }
        }
    } else {
        // both lane bits: shuffle + predicated select
        const bool cset = (lane >> BC) & 1;
#pragma unroll
        for (int k = 0; k < 8; ++k) {
            float px = __shfl_xor_sync(FULL, a[k].x, 1 << BT);
            float py = __shfl_xor_sync(FULL, a[k].y, 1 << BT);
            if (cset) { a[k].x = px; a[k].y = py; }
        }
    }
}

// ---------------------------------------------------------------------------
// Main quantum-layer kernel: one warp per (bs, h) token.
// x: [BS, 64]; token angles = x[bs, h*8 + w]. Writes g_q[bs*64 + h*8 + w].
// ---------------------------------------------------------------------------
__global__ void __launch_bounds__(256)
qlayer_kernel(const float* __restrict__ x,
              const float* __restrict__ params_rx,
              const float* __restrict__ params_rz,
              float* __restrict__ q_out,
              int n_warps, int depth)
{
    __shared__ float cRx[64], sRx[64], cRz[64], sRz[64];  // up to depth 8

    const int tid = threadIdx.x;
    const int dp8 = depth * 8;
    if (tid < dp8) {
        float s_, c_;
        sincosf(params_rx[tid] * 0.5f, &s_, &c_);
        sRx[tid] = s_; cRx[tid] = c_;
    } else if (tid < 2 * dp8) {
        const int i = tid - dp8;
        float s_, c_;
        sincosf(params_rz[i] * 0.5f, &s_, &c_);
        sRz[i] = s_; cRz[i] = c_;
    }
    __syncthreads();

    const int warp_global = blockIdx.x * (blockDim.x >> 5) + (tid >> 5);
    if (warp_global >= n_warps) return;
    const int lane = tid & 31;
    const int bs = warp_global >> 3;
    const int h  = warp_global & 7;

    // Per-token encoding angles: lane w (w<8) computes cos/sin of x/2 for wire w.
    float myc = 0.f, mys = 0.f;
    if (lane < 8) {
        sincosf(x[bs * 64 + h * 8 + lane] * 0.5f, &mys, &myc);
    }

    // init |0...0>
    float2 a[8];
#pragma unroll
    for (int k = 0; k < 8; ++k) a[k] = make_float2(0.f, 0.f);
    if (lane == 0) a[0].x = 1.f;

    // --- data encoding: RX(x_w) on each wire ---
#define APPLY_ENC(W) do {                                \
        float c_ = __shfl_sync(FULL, myc, (W));          \
        float s_ = __shfl_sync(FULL, mys, (W));          \
        rx_wire<(W)>(a, c_, s_);                         \
    } while (0)
    APPLY_ENC(0); APPLY_ENC(1); APPLY_ENC(2); APPLY_ENC(3);
    APPLY_ENC(4); APPLY_ENC(5); APPLY_ENC(6); APPLY_ENC(7);
#undef APPLY_ENC

    // --- variational layers ---
    for (int l = 0; l < depth; ++l) {
        const int base = l * 8;
#define APPLY_LW(W) do {                                          \
            rx_wire<(W)>(a, cRx[base + (W)], sRx[base + (W)]);    \
            rz_wire<(W)>(a, lane, cRz[base + (W)], sRz[base + (W)]); \
        } while (0)
        APPLY_LW(0); APPLY_LW(1); APPLY_LW(2); APPLY_LW(3);
        APPLY_LW(4); APPLY_LW(5); APPLY_LW(6); APPLY_LW(7);
#undef APPLY_LW
        // CNOT ring: (wire w -> w+1) = bits (7-w, 6-w), then (wire7 -> wire0) = bits (0,7)
        cnot<7, 6>(a, lane);
        cnot<6, 5>(a, lane);
        cnot<5, 4>(a, lane);
        cnot<4, 3>(a, lane);
        cnot<3, 2>(a, lane);
        cnot<2, 1>(a, lane);
        cnot<1, 0>(a, lane);
        cnot<0, 7>(a, lane);
    }

    // --- PauliZ expectations ---
    float p[8];
#pragma unroll
    for (int k = 0; k < 8; ++k)
        p[k] = fmaf(a[k].x, a[k].x, a[k].y * a[k].y);

    float sA = 0.f, s0 = 0.f, s1 = 0.f, s2 = 0.f;
#pragma unroll
    for (int k = 0; k < 8; ++k) {
        sA += p[k];
        s0 += ((k >> 2) & 1) ? -p[k] : p[k];  // wire0 <-> idx bit7 <-> k bit2
        s1 += ((k >> 1) & 1) ? -p[k] : p[k];  // wire1
        s2 += ((k     ) & 1) ? -p[k] : p[k];  // wire2
    }

    float z0 = s0, z1 = s1, z2 = s2;
    float z3 = ((lane >> 4) & 1) ? -sA : sA;  // wire3 <-> lane bit4
    float z4 = ((lane >> 3) & 1) ? -sA : sA;
    float z5 = ((lane >> 2) & 1) ? -sA : sA;
    float z6 = ((lane >> 1) & 1) ? -sA : sA;
    float z7 = ((lane     ) & 1) ? -sA : sA;

#pragma unroll
    for (int off = 16; off; off >>= 1) {
        z0 += __shfl_xor_sync(FULL, z0, off);
        z1 += __shfl_xor_sync(FULL, z1, off);
        z2 += __shfl_xor_sync(FULL, z2, off);
        z3 += __shfl_xor_sync(FULL, z3, off);
        z4 += __shfl_xor_sync(FULL, z4, off);
        z5 += __shfl_xor_sync(FULL, z5, off);
        z6 += __shfl_xor_sync(FULL, z6, off);
        z7 += __shfl_xor_sync(FULL, z7, off);
    }

    if (lane == 0) {
        float* q = q_out + bs * 64 + h * 8;
        q[0] = z0; q[1] = z1; q[2] = z2; q[3] = z3;
        q[4] = z4; q[5] = z5; q[6] = z6; q[7] = z7;
    }
}

// ---------------------------------------------------------------------------
// Combine: out[bs, e] = sum_j q[bs, j] * W[e, j]   (out = q @ W^T)
// ---------------------------------------------------------------------------
__global__ void __launch_bounds__(256)
combine_kernel(const float* __restrict__ q,
               const float* __restrict__ W,
               float* __restrict__ out, int BS)
{
    __shared__ float Ws[64][65];   // padded to kill bank conflicts
    __shared__ float qs[16][64];

    for (int i = threadIdx.x; i < 64 * 64; i += blockDim.x)
        Ws[i >> 6][i & 63] = W[i];

    const int row0 = blockIdx.x * 16;
    for (int i = threadIdx.x; i < 16 * 64; i += blockDim.x) {
        const int r = row0 + (i >> 6);
        qs[i >> 6][i & 63] = (r < BS) ? q[r * 64 + (i & 63)] : 0.f;
    }
    __syncthreads();

    for (int o = threadIdx.x; o < 16 * 64; o += blockDim.x) {
        const int r = o >> 6, e = o & 63;
        if (row0 + r >= BS) continue;
        float acc = 0.f;
#pragma unroll
        for (int j = 0; j < 64; ++j)
            acc = fmaf(qs[r][j], Ws[e][j], acc);
        out[(row0 + r) * 64 + e] = acc;
    }
}

// ---------------------------------------------------------------------------
extern "C" void kernel_launch(void* const* d_in, const int* in_sizes, int n_in,
                              void* d_out, int out_size)
{
    const float* x    = (const float*)d_in[0];      // [B,S,64]
    const float* prx  = (const float*)d_in[1];      // [depth,8]
    const float* prz  = (const float*)d_in[2];      // [depth,8]
    const float* W    = (const float*)d_in[3];      // [64,64]
    float* out        = (float*)d_out;              // [B,S,64]

    const int BS    = in_sizes[0] / 64;             // 2048
    const int depth = in_sizes[1] / 8;              // 2
    const int n_warps = BS * 8;                     // 16384 tokens

    float* qbuf = nullptr;
    cudaGetSymbolAddress((void**)&qbuf, g_q);

    const int warps_per_block = 8;                  // 256 threads
    const int grid1 = (n_warps + warps_per_block - 1) / warps_per_block;
    qlayer_kernel<<<grid1, 256>>>(x, prx, prz, qbuf, n_warps, depth);

    const int grid2 = (BS + 15) / 16;
    combine_kernel<<<grid2, 256>>>(qbuf, W, out, BS);
}

// round 2
// speedup vs baseline: 1.8129x; 1.8129x over previous
#include <cuda_runtime.h>
#include <cuda_bf16.h>
#include <cstdint>

#define FULL 0xFFFFFFFFu

// Scratch for qlayer outputs: [BS, 64] floats.
__device__ float g_q[1 << 18];

__device__ __forceinline__ float2 cmul(float2 a, float2 b) {
    return make_float2(fmaf(a.x, b.x, -a.y * b.y),
                       fmaf(a.x, b.y,  a.y * b.x));
}

// ---------------------------------------------------------------------------
// Layout: one warp per token. Lane l holds amplitudes flat=(k<<5)|l, k=0..7.
// Wire w <-> flat bit (7-w). flat bits 0..4 = lane bits (wires 7..3),
// flat bits 5..7 = k bits k0,k1,k2 (wires 2,1,0).
// ---------------------------------------------------------------------------

template<int RB>
__device__ __forceinline__ void rx_reg(float2 (&a)[8], float c, float s) {
#pragma unroll
    for (int k0 = 0; k0 < 8; ++k0) {
        if (k0 & (1 << RB)) continue;
        const int k1 = k0 | (1 << RB);
        float2 A = a[k0], B = a[k1];
        a[k0].x = fmaf(c, A.x,  s * B.y);
        a[k0].y = fmaf(c, A.y, -s * B.x);
        a[k1].x = fmaf(c, B.x,  s * A.y);
        a[k1].y = fmaf(c, B.y, -s * A.x);
    }
}

template<int B>
__device__ __forceinline__ void rx_lane(float2 (&a)[8], float c, float s) {
#pragma unroll
    for (int k = 0; k < 8; ++k) {
        float px = __shfl_xor_sync(FULL, a[k].x, 1 << B);
        float py = __shfl_xor_sync(FULL, a[k].y, 1 << B);
        float nx = fmaf(c, a[k].x,  s * py);
        float ny = fmaf(c, a[k].y, -s * px);
        a[k].x = nx; a[k].y = ny;
    }
}

template<int W>
__device__ __forceinline__ void rx_wire(float2 (&a)[8], float c, float s) {
    constexpr int B = 7 - W;
    if constexpr (B >= 5) rx_reg<B - 5>(a, c, s);
    else                  rx_lane<B>(a, c, s);
}

template<int W>
__device__ __forceinline__ void rz_wire(float2 (&a)[8], int lane, float c, float s) {
    constexpr int B = 7 - W;
#pragma unroll
    for (int k = 0; k < 8; ++k) {
        int bit;
        if constexpr (B >= 5) bit = (k >> (B - 5)) & 1;
        else                  bit = (lane >> B) & 1;
        float t = bit ? s : -s;
        float nx = fmaf(a[k].x, c, -a[k].y * t);
        float ny = fmaf(a[k].y, c,  a[k].x * t);
        a[k].x = nx; a[k].y = ny;
    }
}

template<int BC, int BT>
__device__ __forceinline__ void cnot(float2 (&a)[8], int lane) {
    if constexpr (BC >= 5 && BT >= 5) {
#pragma unroll
        for (int k = 0; k < 8; ++k) {
            if ((k & (1 << (BC - 5))) && !(k & (1 << (BT - 5)))) {
                const int k2 = k | (1 << (BT - 5));
                float2 t = a[k]; a[k] = a[k2]; a[k2] = t;
            }
        }
    } else if constexpr (BC >= 5 && BT < 5) {
#pragma unroll
        for (int k = 0; k < 8; ++k) {
            if (k & (1 << (BC - 5))) {
                a[k].x = __shfl_xor_sync(FULL, a[k].x, 1 << BT);
                a[k].y = __shfl_xor_sync(FULL, a[k].y, 1 << BT);
            }
        }
    } else if constexpr (BC < 5 && BT >= 5) {
        const bool cset = (lane >> BC) & 1;
#pragma unroll
        for (int k0 = 0; k0 < 8; ++k0) {
            if (!(k0 & (1 << (BT - 5)))) {
                const int k1 = k0 | (1 << (BT - 5));
                float2 A = a[k0], B = a[k1];
                a[k0] = cset ? B : A;
                a[k1] = cset ? A : B;
            }
        }
    } else {
        const bool cset = (lane >> BC) & 1;
#pragma unroll
        for (int k = 0; k < 8; ++k) {
            float px = __shfl_xor_sync(FULL, a[k].x, 1 << BT);
            float py = __shfl_xor_sync(FULL, a[k].y, 1 << BT);
            if (cset) { a[k].x = px; a[k].y = py; }
        }
    }
}

// ---------------------------------------------------------------------------
__global__ void __launch_bounds__(256)
qlayer_kernel(const float* __restrict__ x,
              const float* __restrict__ params_rx,
              const float* __restrict__ params_rz,
              float* __restrict__ q_out,
              int n_warps, int depth)
{
    __shared__ float cRx[64], sRx[64], cRz[64], sRz[64];

    const int tid = threadIdx.x;
    const int dp8 = depth * 8;
    if (tid < dp8) {
        float s_, c_;
        sincosf(params_rx[tid] * 0.5f, &s_, &c_);
        sRx[tid] = s_; cRx[tid] = c_;
    } else if (tid < 2 * dp8) {
        const int i = tid - dp8;
        float s_, c_;
        sincosf(params_rz[i] * 0.5f, &s_, &c_);
        sRz[i] = s_; cRz[i] = c_;
    }
    __syncthreads();

    const int warp_global = blockIdx.x * (blockDim.x >> 5) + (tid >> 5);
    if (warp_global >= n_warps) return;
    const int lane = tid & 31;
    const int bs = warp_global >> 3;
    const int h  = warp_global & 7;

    // ---- Fused encoding + layer-0 RX: phi_w = x_w + prx[0,w] ----
    float myc = 0.f, mys = 0.f;
    if (lane < 8) {
        const float ang = x[bs * 64 + h * 8 + lane] + params_rx[lane];
        sincosf(ang * 0.5f, &mys, &myc);
    }

    float uc[8], us[8];
#pragma unroll
    for (int w = 0; w < 8; ++w) {
        uc[w] = __shfl_sync(FULL, myc, w);
        us[w] = __shfl_sync(FULL, mys, w);
    }

    // Per-wire single-qubit vectors after layer-0 RZ:
    // u0 = e^{-i th/2} cos, u1 = -i e^{i th/2} sin
    float2 u0[8], u1[8];
#pragma unroll
    for (int w = 0; w < 8; ++w) {
        const float cz = cRz[w], sz = sRz[w];
        u0[w] = make_float2( cz * uc[w], -sz * uc[w]);
        u1[w] = make_float2( sz * us[w], -cz * us[w]);
    }

    // ---- Direct construction of Ring0( product state ) ----
    // chi(i) = prod_w u_w( sigma_w(i) ), sigma from the CNOT-ring permutation:
    // w0: f7^f0  w1: f6^f7^f0  w2: f5^f6  w3: f4^f5
    // w4: f3^f4  w5: f2^f3     w6: f1^f2  w7: f0^f1   (f = flat-index bits)
    const int f0 = lane & 1, f1 = (lane >> 1) & 1, f2 = (lane >> 2) & 1;
    const int f3 = (lane >> 3) & 1, f4 = (lane >> 4) & 1;

    const int b4 = f3 ^ f4, b5 = f2 ^ f3, b6 = f1 ^ f2, b7 = f0 ^ f1;
    float2 L = cmul(cmul(b4 ? u1[4] : u0[4], b5 ? u1[5] : u0[5]),
                    cmul(b6 ? u1[6] : u0[6], b7 ? u1[7] : u0[7]));

    // A indexed by j = (k2<<1)|k1 ; B by j = (k1<<1)|k0
    float2 A[4], B[4];
#pragma unroll
    for (int j = 0; j < 4; ++j) {
        const int jk2 = j >> 1, jk1 = j & 1;
        A[j] = cmul((jk2 ^ f0) ? u1[0] : u0[0],
                    (jk1 ^ jk2 ^ f0) ? u1[1] : u0[1]);
    }
#pragma unroll
    for (int j = 0; j < 4; ++j) {
        const int jk1 = j >> 1, jk0 = j & 1;
        B[j] = cmul((jk0 ^ jk1) ? u1[2] : u0[2],
                    (f4 ^ jk0) ? u1[3] : u0[3]);
    }

    float2 a[8];
#pragma unroll
    for (int k = 0; k < 8; ++k)
        a[k] = cmul(L, cmul(A[(k >> 1) & 3], B[k & 3]));

    // ---- Middle layers (full), l = 1 .. depth-2 ----
    for (int l = 1; l < depth - 1; ++l) {
        const int base = l * 8;
#define APPLY_LW(W) do {                                             \
            rx_wire<(W)>(a, cRx[base + (W)], sRx[base + (W)]);       \
            rz_wire<(W)>(a, lane, cRz[base + (W)], sRz[base + (W)]); \
        } while (0)
        APPLY_LW(0); APPLY_LW(1); APPLY_LW(2); APPLY_LW(3);
        APPLY_LW(4); APPLY_LW(5); APPLY_LW(6); APPLY_LW(7);
#undef APPLY_LW
        cnot<7, 6>(a, lane);
        cnot<6, 5>(a, lane);
        cnot<5, 4>(a, lane);
        cnot<4, 3>(a, lane);
        cnot<3, 2>(a, lane);
        cnot<2, 1>(a, lane);
        cnot<1, 0>(a, lane);
        cnot<0, 7>(a, lane);
    }

    float z0, z1, z2, z3, z4, z5, z6, z7;

    if (depth >= 2) {
        // ---- Last layer: RX only (RZ dropped, ring folded into observables) ----
        const int base = (depth - 1) * 8;
        rx_wire<0>(a, cRx[base + 0], sRx[base + 0]);
        rx_wire<1>(a, cRx[base + 1], sRx[base + 1]);
        rx_wire<2>(a, cRx[base + 2], sRx[base + 2]);
        rx_wire<3>(a, cRx[base + 3], sRx[base + 3]);
        rx_wire<4>(a, cRx[base + 4], sRx[base + 4]);
        rx_wire<5>(a, cRx[base + 5], sRx[base + 5]);
        rx_wire<6>(a, cRx[base + 6], sRx[base + 6]);
        rx_wire<7>(a, cRx[base + 7], sRx[base + 7]);

        float p[8];
#pragma unroll
        for (int k = 0; k < 8; ++k)
            p[k] = fmaf(a[k].x, a[k].x, a[k].y * a[k].y);

        // Folded observables: Z0 -> Z1..Z7 ; Zw -> Z0..Zw (w>=1)
        float sK = 0.f, s01 = 0.f, s12 = 0.f;
#pragma unroll
        for (int k = 0; k < 8; ++k) {
            const int pk  = __popc(k) & 1;          // k0^k1^k2
            const int p01 = __popc(k & 3) & 1;      // k0^k1
            const int p12 = __popc(k >> 1) & 1;     // k1^k2
            sK  += pk  ? -p[k] : p[k];
            s01 += p01 ? -p[k] : p[k];
            s12 += p12 ? -p[k] : p[k];
        }

        const int m3 = f4;
        const int m4 = m3 ^ f3;
        const int m5 = m4 ^ f2;
        const int m6 = m5 ^ f1;
        const int m7 = m6 ^ f0;

        z0 = m7 ? -s01 : s01;
        z1 = s12;
        z2 = sK;
        z3 = m3 ? -sK : sK;
        z4 = m4 ? -sK : sK;
        z5 = m5 ? -sK : sK;
        z6 = m6 ? -sK : sK;
        z7 = m7 ? -sK : sK;
    } else {
        // depth == 1: ring already applied in construction; plain observables.
        float p[8];
#pragma unroll
        for (int k = 0; k < 8; ++k)
            p[k] = fmaf(a[k].x, a[k].x, a[k].y * a[k].y);
        float sA = 0.f, s0 = 0.f, s1 = 0.f, s2 = 0.f;
#pragma unroll
        for (int k = 0; k < 8; ++k) {
            sA += p[k];
            s0 += ((k >> 2) & 1) ? -p[k] : p[k];
            s1 += ((k >> 1) & 1) ? -p[k] : p[k];
            s2 += ((k     ) & 1) ? -p[k] : p[k];
        }
        z0 = s0; z1 = s1; z2 = s2;
        z3 = f4 ? -sA : sA;
        z4 = f3 ? -sA : sA;
        z5 = f2 ? -sA : sA;
        z6 = f1 ? -sA : sA;
        z7 = f0 ? -sA : sA;
    }

#pragma unroll
    for (int off = 16; off; off >>= 1) {
        z0 += __shfl_xor_sync(FULL, z0, off);
        z1 += __shfl_xor_sync(FULL, z1, off);
        z2 += __shfl_xor_sync(FULL, z2, off);
        z3 += __shfl_xor_sync(FULL, z3, off);
        z4 += __shfl_xor_sync(FULL, z4, off);
        z5 += __shfl_xor_sync(FULL, z5, off);
        z6 += __shfl_xor_sync(FULL, z6, off);
        z7 += __shfl_xor_sync(FULL, z7, off);
    }

    if (lane == 0) {
        float* q = q_out + bs * 64 + h * 8;
        q[0] = z0; q[1] = z1; q[2] = z2; q[3] = z3;
        q[4] = z4; q[5] = z5; q[6] = z6; q[7] = z7;
    }
}

// ---------------------------------------------------------------------------
// Combine: out[r, e] = sum_j q[r, j] * W[e, j].  W^T staged in padded smem,
// each thread produces a float4 of outputs: 1 LDS + 1 LDS.128 per 4 FMA.
// ---------------------------------------------------------------------------
__global__ void __launch_bounds__(256)
combine_kernel(const float* __restrict__ q,
               const float* __restrict__ W,
               float* __restrict__ out, int BS)
{
    __shared__ float Wt[64 * 68];    // Wt[j*68 + e] = W[e][j]; 272B rows (16B-aligned)
    __shared__ float qs[16 * 64];

    const int tid = threadIdx.x;
    for (int i = tid; i < 4096; i += 256) {
        const int e = i >> 6, j = i & 63;
        Wt[j * 68 + e] = W[i];
    }
    const int row0 = blockIdx.x * 16;
    for (int i = tid; i < 1024; i += 256) {
        const int r = row0 + (i >> 6);
        qs[i] = (r < BS) ? q[r * 64 + (i & 63)] : 0.f;
    }
    __syncthreads();

    const int e4 = tid & 15;          // output quad (4 cols)
    const int r  = tid >> 4;          // row within block
    const float* qrow = &qs[r * 64];

    float4 acc = make_float4(0.f, 0.f, 0.f, 0.f);
#pragma unroll
    for (int j = 0; j < 64; ++j) {
        const float qj = qrow[j];
        const float4 w4 = *reinterpret_cast<const float4*>(&Wt[j * 68 + e4 * 4]);
        acc.x = fmaf(qj, w4.x, acc.x);
        acc.y = fmaf(qj, w4.y, acc.y);
        acc.z = fmaf(qj, w4.z, acc.z);
        acc.w = fmaf(qj, w4.w, acc.w);
    }

    if (row0 + r < BS)
        *reinterpret_cast<float4*>(&out[(row0 + r) * 64 + e4 * 4]) = acc;
}

// ---------------------------------------------------------------------------
extern "C" void kernel_launch(void* const* d_in, const int* in_sizes, int n_in,
                              void* d_out, int out_size)
{
    const float* x    = (const float*)d_in[0];      // [B,S,64]
    const float* prx  = (const float*)d_in[1];      // [depth,8]
    const float* prz  = (const float*)d_in[2];      // [depth,8]
    const float* W    = (const float*)d_in[3];      // [64,64]
    float* out        = (float*)d_out;              // [B,S,64]

    const int BS    = in_sizes[0] / 64;
    const int depth = in_sizes[1] / 8;
    const int n_warps = BS * 8;

    float* qbuf = nullptr;
    cudaGetSymbolAddress((void**)&qbuf, g_q);

    const int warps_per_block = 8;
    const int grid1 = (n_warps + warps_per_block - 1) / warps_per_block;
    qlayer_kernel<<<grid1, 256>>>(x, prx, prz, qbuf, n_warps, depth);

    const int grid2 = (BS + 15) / 16;
    combine_kernel<<<grid2, 256>>>(qbuf, W, out, BS);
}